// round 8
// baseline (speedup 1.0000x reference)
#include <cuda_runtime.h>
#include <cstdint>

// Problem-shape capacities (fixed by the dataset: N=100000, E=3200000)
#define NCAP 100000
#define ECAP 3200000
#define SCANB 512                       // level-1 scan block size
#define NBMAX ((NCAP + SCANB - 1) / SCANB)   // 196 <= 256

// Static device scratch. float4-typed feature buffers => 16B-aligned.
__device__ float  g_deg  [NCAP];
__device__ float  g_dinv [NCAP];
__device__ int    g_cnt  [NCAP];        // per-dst edge count
__device__ int    g_start[NCAP];        // CSR row start (exclusive scan of cnt)
__device__ int    g_pos  [NCAP];        // scatter fill cursor
__device__ int    g_bsum [NBMAX];       // scan block sums
__device__ float2 g_csr  [ECAP];        // dst-sorted: {src (bits), w}
__device__ float4 g_hs1  [NCAP * 8];    // (x@W1)*dinv[row]   (32 f/row)
__device__ float4 g_z1   [NCAP * 8];    // relu layer-1 output
__device__ float4 g_hs2  [NCAP * 4];    // (z1@W2)*dinv[row]  (16 f/row)

// ---------------------------------------------------------------------------
// init: cnt=0, deg=1 (self-loop weight)
__global__ void k_init(int N) {
    int i = blockIdx.x * blockDim.x + threadIdx.x;
    if (i < N) { g_cnt[i] = 0; g_deg[i] = 1.0f; }
}

// histogram + weighted degree in one pass (edge_index int32, layout [2,E])
__global__ void k_hist(const int* __restrict__ ei,
                       const float* __restrict__ ew, int E) {
    int e = blockIdx.x * blockDim.x + threadIdx.x;
    if (e >= E) return;
    int dst = __ldg(ei + E + e);
    atomicAdd(&g_cnt[dst], 1);
    atomicAdd(&g_deg[dst], __ldg(ew + e));
}

// scan level 1: per-block inclusive scan of cnt -> exclusive in g_start,
// block total in g_bsum
__global__ void k_scan1(int N) {
    __shared__ int s[SCANB];
    int tid = threadIdx.x;
    int i = blockIdx.x * SCANB + tid;
    int v = (i < N) ? g_cnt[i] : 0;
    s[tid] = v; __syncthreads();
#pragma unroll
    for (int off = 1; off < SCANB; off <<= 1) {
        int t = (tid >= off) ? s[tid - off] : 0;
        __syncthreads();
        s[tid] += t;
        __syncthreads();
    }
    if (i < N) g_start[i] = s[tid] - v;
    if (tid == SCANB - 1) g_bsum[blockIdx.x] = s[tid];
}

// scan level 2: single block scans the <=256 block sums (exclusive)
__global__ void k_scan2(int NB) {
    __shared__ int s[256];
    int tid = threadIdx.x;
    int v = (tid < NB) ? g_bsum[tid] : 0;
    s[tid] = v; __syncthreads();
#pragma unroll
    for (int off = 1; off < 256; off <<= 1) {
        int t = (tid >= off) ? s[tid - off] : 0;
        __syncthreads();
        s[tid] += t;
        __syncthreads();
    }
    if (tid < NB) g_bsum[tid] = s[tid] - v;
}

// scan level 3: finalize starts, init fill cursors, compute dinv
__global__ void k_scan3(int N) {
    int i = blockIdx.x * blockDim.x + threadIdx.x;
    if (i >= N) return;
    int st = g_start[i] + g_bsum[i / SCANB];
    g_start[i] = st;
    g_pos[i]   = st;
    float d = g_deg[i];
    g_dinv[i] = (d > 0.0f) ? rsqrtf(d) : 0.0f;
}

// scatter edges into dst-sorted CSR: {src, w} packed as float2
__global__ void k_scatter(const int* __restrict__ ei,
                          const float* __restrict__ ew, int E) {
    int e = blockIdx.x * blockDim.x + threadIdx.x;
    if (e >= E) return;
    int src = __ldg(ei + e);
    int dst = __ldg(ei + E + e);
    float w = __ldg(ew + e);
    int p = atomicAdd(&g_pos[dst], 1);
    g_csr[p] = make_float2(__int_as_float(src), w);
}

// ---------------------------------------------------------------------------
// Register-tiled GEMM (TM=4, BM=128 — R6's measured-best config).
// LAYER==1: X = raw input x. LAYER==2: X = g_z1.
// Epilogue: hs<LAYER>[row] = (X[row] @ W) * dinv[row].
template <int FIN, int FOUT, int LAYER>
__global__ void __launch_bounds__(32 * (FOUT / 4))
k_gemm_tiled(const float* __restrict__ Xin,
             const float* __restrict__ W, int N) {
    constexpr int NCT = FOUT / 4;       // 8 (L1) or 4 (L2)
    constexpr int TM  = 4;
    constexpr int BM  = 32 * TM;        // 128 rows/block
    constexpr int NT  = NCT * 32;

    __shared__ float sW[FIN * FOUT];
    for (int i = threadIdx.x; i < FIN * FOUT / 4; i += NT)
        reinterpret_cast<float4*>(sW)[i] =
            __ldg(reinterpret_cast<const float4*>(W) + i);
    __syncthreads();

    const float* X = (LAYER == 1) ? Xin : reinterpret_cast<const float*>(g_z1);
    const int ci = threadIdx.x % NCT;
    const int ri = threadIdx.x / NCT;
    const int r0 = blockIdx.x * BM + ri * TM;
    const bool full = (r0 + TM <= N);

    float acc[TM][4];
#pragma unroll
    for (int t = 0; t < TM; t++)
#pragma unroll
        for (int j = 0; j < 4; j++) acc[t][j] = 0.0f;

#pragma unroll 4
    for (int k4 = 0; k4 < FIN / 4; k4++) {
        float xr[TM][4];
#pragma unroll
        for (int t = 0; t < TM; t++) {
            float4 v = make_float4(0.f, 0.f, 0.f, 0.f);
            int r = r0 + t;
            if (full || r < N)
                v = __ldg(reinterpret_cast<const float4*>(X + (size_t)r * FIN) + k4);
            xr[t][0] = v.x; xr[t][1] = v.y; xr[t][2] = v.z; xr[t][3] = v.w;
        }
#pragma unroll
        for (int kk = 0; kk < 4; kk++) {
            float4 wv = *reinterpret_cast<const float4*>(
                &sW[(k4 * 4 + kk) * FOUT + ci * 4]);
#pragma unroll
            for (int t = 0; t < TM; t++) {
                float xs = xr[t][kk];
                acc[t][0] += xs * wv.x;
                acc[t][1] += xs * wv.y;
                acc[t][2] += xs * wv.z;
                acc[t][3] += xs * wv.w;
            }
        }
    }

    float4* HS = (LAYER == 1) ? g_hs1 : g_hs2;
#pragma unroll
    for (int t = 0; t < TM; t++) {
        int r = r0 + t;
        if (full || r < N) {
            float s = g_dinv[r];
            HS[(size_t)r * NCT + ci] = make_float4(acc[t][0] * s, acc[t][1] * s,
                                                   acc[t][2] * s, acc[t][3] * s);
        }
    }
}

// ---------------------------------------------------------------------------
// CSR aggregation layer 1: warp per node. 4 edge-groups x 8 chunk-threads.
// z1[node] = relu(dinv*(sum_e w*hs1[src] + hs1[node]) + b1)  (fused post)
__global__ void k_agg1(const float* __restrict__ b1, int N) {
    int warp = (blockIdx.x * blockDim.x + threadIdx.x) >> 5;
    if (warp >= N) return;
    int lane = threadIdx.x & 31;
    int c  = lane & 7;        // feature chunk (float4)
    int eg = lane >> 3;       // edge group 0..3

    int start = g_start[warp];
    int cnt   = g_cnt[warp];

    float4 acc = make_float4(0.f, 0.f, 0.f, 0.f);
    for (int k = eg; k < cnt; k += 4) {
        float2 ed = __ldg(g_csr + start + k);
        int   src = __float_as_int(ed.x);
        float w   = ed.y;
        float4 v  = __ldg(g_hs1 + (size_t)src * 8 + c);
        acc.x += w * v.x; acc.y += w * v.y;
        acc.z += w * v.z; acc.w += w * v.w;
    }
    // reduce over the 4 edge groups (lanes {c, c+8, c+16, c+24})
#pragma unroll
    for (int m = 8; m <= 16; m <<= 1) {
        acc.x += __shfl_xor_sync(0xffffffffu, acc.x, m);
        acc.y += __shfl_xor_sync(0xffffffffu, acc.y, m);
        acc.z += __shfl_xor_sync(0xffffffffu, acc.z, m);
        acc.w += __shfl_xor_sync(0xffffffffu, acc.w, m);
    }
    if (eg == 0) {
        float  s  = g_dinv[warp];
        float4 h  = __ldg(g_hs1 + (size_t)warp * 8 + c);
        float4 bb = __ldg(reinterpret_cast<const float4*>(b1) + c);
        float4 z;
        z.x = fmaxf(s * (acc.x + h.x) + bb.x, 0.0f);
        z.y = fmaxf(s * (acc.y + h.y) + bb.y, 0.0f);
        z.z = fmaxf(s * (acc.z + h.z) + bb.z, 0.0f);
        z.w = fmaxf(s * (acc.w + h.w) + bb.w, 0.0f);
        g_z1[(size_t)warp * 8 + c] = z;
    }
}

// ---------------------------------------------------------------------------
// CSR aggregation layer 2 + fused final linear.
// 8 edge-groups x 4 chunk-threads; epilogue computes
// z2 = relu(dinv*(acc+hs2)+b2) and out = z2 @ Wout + bout  (16 -> 3).
__global__ void k_agg2_out(const float* __restrict__ b2,
                           const float* __restrict__ Wout,
                           const float* __restrict__ bout,
                           float* __restrict__ out, int N) {
    __shared__ float sW[48];
    __shared__ float sb[3];
    if (threadIdx.x < 48) sW[threadIdx.x] = __ldg(Wout + threadIdx.x);
    if (threadIdx.x < 3)  sb[threadIdx.x] = __ldg(bout + threadIdx.x);
    __syncthreads();

    int warp = (blockIdx.x * blockDim.x + threadIdx.x) >> 5;
    if (warp >= N) return;
    int lane = threadIdx.x & 31;
    int c  = lane & 3;        // feature chunk (float4), 4 chunks = 16 floats
    int eg = lane >> 2;       // edge group 0..7

    int start = g_start[warp];
    int cnt   = g_cnt[warp];

    float4 acc = make_float4(0.f, 0.f, 0.f, 0.f);
    for (int k = eg; k < cnt; k += 8) {
        float2 ed = __ldg(g_csr + start + k);
        int   src = __float_as_int(ed.x);
        float w   = ed.y;
        float4 v  = __ldg(g_hs2 + (size_t)src * 4 + c);
        acc.x += w * v.x; acc.y += w * v.y;
        acc.z += w * v.z; acc.w += w * v.w;
    }
#pragma unroll
    for (int m = 4; m <= 16; m <<= 1) {
        acc.x += __shfl_xor_sync(0xffffffffu, acc.x, m);
        acc.y += __shfl_xor_sync(0xffffffffu, acc.y, m);
        acc.z += __shfl_xor_sync(0xffffffffu, acc.z, m);
        acc.w += __shfl_xor_sync(0xffffffffu, acc.w, m);
    }
    // lanes 0..3 (eg==0) hold the 4 final chunks
    float  s  = g_dinv[warp];
    float4 h  = __ldg(g_hs2 + (size_t)warp * 4 + c);
    float4 bb = __ldg(reinterpret_cast<const float4*>(b2) + c);
    float z[4];
    z[0] = fmaxf(s * (acc.x + h.x) + bb.x, 0.0f);
    z[1] = fmaxf(s * (acc.y + h.y) + bb.y, 0.0f);
    z[2] = fmaxf(s * (acc.z + h.z) + bb.z, 0.0f);
    z[3] = fmaxf(s * (acc.w + h.w) + bb.w, 0.0f);

    // partial 16x3 matvec from this lane's 4 features (valid in lanes 0..3)
    float a0 = 0.f, a1 = 0.f, a2 = 0.f;
#pragma unroll
    for (int q = 0; q < 4; q++) {
        int kk = c * 4 + q;
        a0 += z[q] * sW[kk * 3 + 0];
        a1 += z[q] * sW[kk * 3 + 1];
        a2 += z[q] * sW[kk * 3 + 2];
    }
    // reduce across lanes 0..3 (closed under xor 1, 2)
#pragma unroll
    for (int m = 1; m <= 2; m <<= 1) {
        a0 += __shfl_xor_sync(0xffffffffu, a0, m);
        a1 += __shfl_xor_sync(0xffffffffu, a1, m);
        a2 += __shfl_xor_sync(0xffffffffu, a2, m);
    }
    if (lane == 0) {
        float* o = out + (size_t)warp * 3;
        o[0] = a0 + sb[0]; o[1] = a1 + sb[1]; o[2] = a2 + sb[2];
    }
}

// ---------------------------------------------------------------------------
extern "C" void kernel_launch(void* const* d_in, const int* in_sizes, int n_in,
                              void* d_out, int out_size) {
    const float* x    = (const float*)d_in[0];
    const int*   ei   = (const int*)d_in[1];     // int32 [2, E]
    const float* ew   = (const float*)d_in[2];
    const float* W1   = (const float*)d_in[3];
    const float* b1   = (const float*)d_in[4];
    const float* W2   = (const float*)d_in[5];
    const float* b2   = (const float*)d_in[6];
    const float* Wout = (const float*)d_in[7];
    const float* bout = (const float*)d_in[8];
    float*       out  = (float*)d_out;

    const int N  = in_sizes[0] / 128;
    const int E  = in_sizes[2];
    const int NB = (N + SCANB - 1) / SCANB;

    const int B = 256;
    auto blocks = [B](long long n) { return (unsigned)((n + B - 1) / B); };

    // --- CSR build (+ degree/dinv) ---
    k_init   <<<blocks(N), B>>>(N);
    k_hist   <<<blocks(E), B>>>(ei, ew, E);
    k_scan1  <<<NB, SCANB>>>(N);
    k_scan2  <<<1, 256>>>(NB);
    k_scan3  <<<blocks(N), B>>>(N);
    k_scatter<<<blocks(E), B>>>(ei, ew, E);

    // --- layer 1 ---
    k_gemm_tiled<128, 32, 1><<<(N + 127) / 128, 256>>>(x, W1, N);
    k_agg1<<<blocks((long long)N * 32), B>>>(b1, N);
    // --- layer 2 ---
    k_gemm_tiled<32, 16, 2><<<(N + 127) / 128, 128>>>(nullptr, W2, N);
    k_agg2_out<<<blocks((long long)N * 32), B>>>(b2, Wout, bout, out, N);
}

// round 9
// speedup vs baseline: 1.0756x; 1.0756x over previous
#include <cuda_runtime.h>
#include <cstdint>

// Problem-shape capacities (fixed by the dataset: N=100000, E=3200000)
#define NCAP 100000
#define ECAP 3200000
#define SCANB 512                            // level-1 scan block size
#define NBMAX ((NCAP + SCANB - 1) / SCANB)   // 196 <= 256

// Static device scratch. Uninitialized __device__ globals are zero-filled at
// module load; kernels restore "zero" invariants after use so every execution
// (correctness run + each graph replay) sees identical initial state.
__device__ float  g_degsum[NCAP];       // sum of incoming w (0 at launch start)
__device__ float  g_dinv  [NCAP];
__device__ int    g_cnt   [NCAP];       // per-dst edge count (0 at launch start)
__device__ int    g_start [NCAP];       // CSR row start
__device__ int    g_pos   [NCAP];       // scatter fill cursor
__device__ int    g_bsum  [NBMAX];      // scan block sums
__device__ float2 g_csr   [ECAP];       // dst-sorted: {src bits, w*dinv[src]}
__device__ float4 g_hs1   [NCAP * 8];   // h1 = x@W1 (raw, 32 f/row)
__device__ float4 g_z1    [NCAP * 8];   // relu layer-1 output
__device__ float4 g_hs2   [NCAP * 4];   // h2 = z1@W2 (raw, 16 f/row)

// ---------------------------------------------------------------------------
// histogram + weighted in-degree (edge_index int32, layout [2,E])
__global__ void k_hist(const int* __restrict__ ei,
                       const float* __restrict__ ew, int E) {
    int e = blockIdx.x * blockDim.x + threadIdx.x;
    if (e >= E) return;
    int dst = __ldg(ei + E + e);
    atomicAdd(&g_cnt[dst], 1);
    atomicAdd(&g_degsum[dst], __ldg(ew + e));
}

// scan level 1: per-block inclusive scan of cnt -> exclusive partial in
// g_start, block total in g_bsum
__global__ void k_scan1(int N) {
    __shared__ int s[SCANB];
    int tid = threadIdx.x;
    int i = blockIdx.x * SCANB + tid;
    int v = (i < N) ? g_cnt[i] : 0;
    s[tid] = v; __syncthreads();
#pragma unroll
    for (int off = 1; off < SCANB; off <<= 1) {
        int t = (tid >= off) ? s[tid - off] : 0;
        __syncthreads();
        s[tid] += t;
        __syncthreads();
    }
    if (i < N) g_start[i] = s[tid] - v;
    if (tid == SCANB - 1) g_bsum[blockIdx.x] = s[tid];
}

// scan level 2+3 merged: every block redundantly exclusive-scans the <=256
// block sums in smem, then finalizes starts/cursors, computes dinv, and
// resets degsum for the next execution.
__global__ void k_scan23(int N, int NB) {
    __shared__ int s[256];
    __shared__ int sx[256];
    int tid = threadIdx.x;
    int v = (tid < NB) ? g_bsum[tid] : 0;
    s[tid] = v; __syncthreads();
#pragma unroll
    for (int off = 1; off < 256; off <<= 1) {
        int t = (tid >= off) ? s[tid - off] : 0;
        __syncthreads();
        s[tid] += t;
        __syncthreads();
    }
    sx[tid] = s[tid] - v;
    __syncthreads();

    int i = blockIdx.x * blockDim.x + tid;
    if (i >= N) return;
    int st = g_start[i] + sx[i / SCANB];
    g_start[i] = st;
    g_pos[i]   = st;
    float d = g_degsum[i] + 1.0f;           // self-loop weight 1 => d >= 1
    g_degsum[i] = 0.0f;                     // restore invariant
    g_dinv[i] = rsqrtf(d);
}

// scatter edges into dst-sorted CSR with src-side norm folded in:
// entry = {src, w * dinv[src]}
__global__ void k_scatter(const int* __restrict__ ei,
                          const float* __restrict__ ew, int E) {
    int e = blockIdx.x * blockDim.x + threadIdx.x;
    if (e >= E) return;
    int src = __ldg(ei + e);
    int dst = __ldg(ei + E + e);
    float w = __ldg(ew + e) * __ldg(g_dinv + src);
    int p = atomicAdd(&g_pos[dst], 1);
    g_csr[p] = make_float2(__int_as_float(src), w);
}

// ---------------------------------------------------------------------------
// Register-tiled GEMM (TM=4, BM=128 — measured-best config). No dinv use,
// so it is fully independent of the CSR/degree chain (stream-overlappable).
// LAYER==1: X = raw input x -> g_hs1. LAYER==2: X = g_z1 -> g_hs2.
template <int FIN, int FOUT, int LAYER>
__global__ void __launch_bounds__(32 * (FOUT / 4))
k_gemm_tiled(const float* __restrict__ Xin,
             const float* __restrict__ W, int N) {
    constexpr int NCT = FOUT / 4;       // 8 (L1) or 4 (L2)
    constexpr int TM  = 4;
    constexpr int BM  = 32 * TM;        // 128 rows/block
    constexpr int NT  = NCT * 32;

    __shared__ float sW[FIN * FOUT];
    for (int i = threadIdx.x; i < FIN * FOUT / 4; i += NT)
        reinterpret_cast<float4*>(sW)[i] =
            __ldg(reinterpret_cast<const float4*>(W) + i);
    __syncthreads();

    const float* X = (LAYER == 1) ? Xin : reinterpret_cast<const float*>(g_z1);
    const int ci = threadIdx.x % NCT;
    const int ri = threadIdx.x / NCT;
    const int r0 = blockIdx.x * BM + ri * TM;
    const bool full = (r0 + TM <= N);

    float acc[TM][4];
#pragma unroll
    for (int t = 0; t < TM; t++)
#pragma unroll
        for (int j = 0; j < 4; j++) acc[t][j] = 0.0f;

#pragma unroll 4
    for (int k4 = 0; k4 < FIN / 4; k4++) {
        float xr[TM][4];
#pragma unroll
        for (int t = 0; t < TM; t++) {
            float4 v = make_float4(0.f, 0.f, 0.f, 0.f);
            int r = r0 + t;
            if (full || r < N)
                v = __ldg(reinterpret_cast<const float4*>(X + (size_t)r * FIN) + k4);
            xr[t][0] = v.x; xr[t][1] = v.y; xr[t][2] = v.z; xr[t][3] = v.w;
        }
#pragma unroll
        for (int kk = 0; kk < 4; kk++) {
            float4 wv = *reinterpret_cast<const float4*>(
                &sW[(k4 * 4 + kk) * FOUT + ci * 4]);
#pragma unroll
            for (int t = 0; t < TM; t++) {
                float xs = xr[t][kk];
                acc[t][0] += xs * wv.x;
                acc[t][1] += xs * wv.y;
                acc[t][2] += xs * wv.z;
                acc[t][3] += xs * wv.w;
            }
        }
    }

    float4* HS = (LAYER == 1) ? g_hs1 : g_hs2;
#pragma unroll
    for (int t = 0; t < TM; t++) {
        int r = r0 + t;
        if (full || r < N)
            HS[(size_t)r * NCT + ci] = make_float4(acc[t][0], acc[t][1],
                                                   acc[t][2], acc[t][3]);
    }
}

// ---------------------------------------------------------------------------
// CSR aggregation layer 1: warp per node, 4 edge-groups x 8 chunk-threads.
// z1 = relu(s*(sum_e w'*h1[src] + s*h1[node]) + b1)   (s = dinv[node])
__global__ void k_agg1(const float* __restrict__ b1, int N) {
    int warp = (blockIdx.x * blockDim.x + threadIdx.x) >> 5;
    if (warp >= N) return;
    int lane = threadIdx.x & 31;
    int c  = lane & 7;        // feature chunk (float4)
    int eg = lane >> 3;       // edge group 0..3

    int start = g_start[warp];
    int cnt   = g_cnt[warp];

    float4 acc = make_float4(0.f, 0.f, 0.f, 0.f);
    for (int k = eg; k < cnt; k += 4) {
        float2 ed = __ldg(g_csr + start + k);
        int   src = __float_as_int(ed.x);
        float w   = ed.y;
        float4 v  = __ldg(g_hs1 + (size_t)src * 8 + c);
        acc.x += w * v.x; acc.y += w * v.y;
        acc.z += w * v.z; acc.w += w * v.w;
    }
#pragma unroll
    for (int m = 8; m <= 16; m <<= 1) {
        acc.x += __shfl_xor_sync(0xffffffffu, acc.x, m);
        acc.y += __shfl_xor_sync(0xffffffffu, acc.y, m);
        acc.z += __shfl_xor_sync(0xffffffffu, acc.z, m);
        acc.w += __shfl_xor_sync(0xffffffffu, acc.w, m);
    }
    if (eg == 0) {
        float  s  = g_dinv[warp];
        float4 h  = __ldg(g_hs1 + (size_t)warp * 8 + c);
        float4 bb = __ldg(reinterpret_cast<const float4*>(b1) + c);
        float4 z;
        z.x = fmaxf(s * (acc.x + s * h.x) + bb.x, 0.0f);
        z.y = fmaxf(s * (acc.y + s * h.y) + bb.y, 0.0f);
        z.z = fmaxf(s * (acc.z + s * h.z) + bb.z, 0.0f);
        z.w = fmaxf(s * (acc.w + s * h.w) + bb.w, 0.0f);
        g_z1[(size_t)warp * 8 + c] = z;
    }
}

// ---------------------------------------------------------------------------
// CSR aggregation layer 2 + fused final linear (16 -> 3).
// Also restores g_cnt = 0 for the next execution.
__global__ void k_agg2_out(const float* __restrict__ b2,
                           const float* __restrict__ Wout,
                           const float* __restrict__ bout,
                           float* __restrict__ out, int N) {
    __shared__ float sW[48];
    __shared__ float sb[3];
    if (threadIdx.x < 48) sW[threadIdx.x] = __ldg(Wout + threadIdx.x);
    if (threadIdx.x < 3)  sb[threadIdx.x] = __ldg(bout + threadIdx.x);
    __syncthreads();

    int warp = (blockIdx.x * blockDim.x + threadIdx.x) >> 5;
    if (warp >= N) return;
    int lane = threadIdx.x & 31;
    int c  = lane & 3;        // feature chunk (float4), 4 chunks = 16 floats
    int eg = lane >> 2;       // edge group 0..7

    int start = g_start[warp];
    int cnt   = g_cnt[warp];

    float4 acc = make_float4(0.f, 0.f, 0.f, 0.f);
    for (int k = eg; k < cnt; k += 8) {
        float2 ed = __ldg(g_csr + start + k);
        int   src = __float_as_int(ed.x);
        float w   = ed.y;
        float4 v  = __ldg(g_hs2 + (size_t)src * 4 + c);
        acc.x += w * v.x; acc.y += w * v.y;
        acc.z += w * v.z; acc.w += w * v.w;
    }
#pragma unroll
    for (int m = 4; m <= 16; m <<= 1) {
        acc.x += __shfl_xor_sync(0xffffffffu, acc.x, m);
        acc.y += __shfl_xor_sync(0xffffffffu, acc.y, m);
        acc.z += __shfl_xor_sync(0xffffffffu, acc.z, m);
        acc.w += __shfl_xor_sync(0xffffffffu, acc.w, m);
    }
    // lanes 0..3 hold the 4 final chunks
    float  s  = g_dinv[warp];
    float4 h  = __ldg(g_hs2 + (size_t)warp * 4 + c);
    float4 bb = __ldg(reinterpret_cast<const float4*>(b2) + c);
    float z[4];
    z[0] = fmaxf(s * (acc.x + s * h.x) + bb.x, 0.0f);
    z[1] = fmaxf(s * (acc.y + s * h.y) + bb.y, 0.0f);
    z[2] = fmaxf(s * (acc.z + s * h.z) + bb.z, 0.0f);
    z[3] = fmaxf(s * (acc.w + s * h.w) + bb.w, 0.0f);

    float a0 = 0.f, a1 = 0.f, a2 = 0.f;
#pragma unroll
    for (int q = 0; q < 4; q++) {
        int kk = c * 4 + q;
        a0 += z[q] * sW[kk * 3 + 0];
        a1 += z[q] * sW[kk * 3 + 1];
        a2 += z[q] * sW[kk * 3 + 2];
    }
#pragma unroll
    for (int m = 1; m <= 2; m <<= 1) {
        a0 += __shfl_xor_sync(0xffffffffu, a0, m);
        a1 += __shfl_xor_sync(0xffffffffu, a1, m);
        a2 += __shfl_xor_sync(0xffffffffu, a2, m);
    }
    if (lane == 0) {
        float* o = out + (size_t)warp * 3;
        o[0] = a0 + sb[0]; o[1] = a1 + sb[1]; o[2] = a2 + sb[2];
        g_cnt[warp] = 0;                    // restore invariant
    }
}

// ---------------------------------------------------------------------------
extern "C" void kernel_launch(void* const* d_in, const int* in_sizes, int n_in,
                              void* d_out, int out_size) {
    const float* x    = (const float*)d_in[0];
    const int*   ei   = (const int*)d_in[1];     // int32 [2, E]
    const float* ew   = (const float*)d_in[2];
    const float* W1   = (const float*)d_in[3];
    const float* b1   = (const float*)d_in[4];
    const float* W2   = (const float*)d_in[5];
    const float* b2   = (const float*)d_in[6];
    const float* Wout = (const float*)d_in[7];
    const float* bout = (const float*)d_in[8];
    float*       out  = (float*)d_out;

    const int N  = in_sizes[0] / 128;
    const int E  = in_sizes[2];
    const int NB = (N + SCANB - 1) / SCANB;

    const int B = 256;
    auto blocks = [B](long long n) { return (unsigned)((n + B - 1) / B); };

    // Side stream + events, created once on the (non-capturing) correctness
    // call; reused during capture for the documented event fork/join pattern.
    static cudaStream_t s_side = nullptr;
    static cudaEvent_t  s_ev0 = nullptr, s_ev1 = nullptr;
    if (s_side == nullptr) {
        cudaStreamCreateWithFlags(&s_side, cudaStreamNonBlocking);
        cudaEventCreateWithFlags(&s_ev0, cudaEventDisableTiming);
        cudaEventCreateWithFlags(&s_ev1, cudaEventDisableTiming);
    }

    // Fork: gemm1 (independent of degree/CSR chain) on the side stream.
    cudaEventRecord(s_ev0, 0);
    cudaStreamWaitEvent(s_side, s_ev0, 0);
    k_gemm_tiled<128, 32, 1><<<(N + 127) / 128, 256, 0, s_side>>>(x, W1, N);
    cudaEventRecord(s_ev1, s_side);

    // Main stream: CSR build (+ dinv), overlapped with gemm1.
    k_hist   <<<blocks(E), B>>>(ei, ew, E);
    k_scan1  <<<NB, SCANB>>>(N);
    k_scan23 <<<blocks(N), B>>>(N, NB);
    k_scatter<<<blocks(E), B>>>(ei, ew, E);

    // Join, then the serial tail.
    cudaStreamWaitEvent(0, s_ev1, 0);
    k_agg1<<<blocks((long long)N * 32), B>>>(b1, N);
    k_gemm_tiled<32, 16, 2><<<(N + 127) / 128, 128>>>(nullptr, W2, N);
    k_agg2_out<<<blocks((long long)N * 32), B>>>(b2, Wout, bout, out, N);
}

// round 11
// speedup vs baseline: 1.1481x; 1.0674x over previous
#include <cuda_runtime.h>
#include <cstdint>

// Problem-shape capacities (fixed by the dataset: N=100000, E=3200000)
#define NCAP 100000
#define ECAP 3200000
#define SCANB 512                            // level-1 scan block size
#define NBMAX ((NCAP + SCANB - 1) / SCANB)   // 196 <= 256

// Static device scratch. Zero-filled at module load; kernels restore "zero"
// invariants after use so every execution (correctness + replays) sees
// identical initial state.
__device__ unsigned long long g_degcnt[NCAP];  // hi24: edge count, lo40: sum(w)*2^24
__device__ float  g_dinv  [NCAP];
__device__ int    g_start [NCAP + 1];   // CSR row starts (+ total at [N])
__device__ int    g_bsum  [NBMAX];      // scan block sums
__device__ int    g_rank  [ECAP];       // per-edge rank within dst bucket
__device__ float2 g_csr   [ECAP];       // dst-sorted: {src bits, w*dinv[src]}
__device__ float4 g_hs1   [NCAP * 8];   // h1 = x@W1 (raw, 32 f/row)
__device__ float4 g_z1    [NCAP * 8];   // relu layer-1 output
__device__ float4 g_hs2   [NCAP * 4];   // h2 = z1@W2 (raw, 16 f/row)

// ---------------------------------------------------------------------------
// histogram: one packed u64 atomic gives edge count, weighted degree, AND the
// edge's rank within its dst bucket (from the returned old value).
__global__ void k_hist(const int* __restrict__ ei,
                       const float* __restrict__ ew, int E) {
    int e = blockIdx.x * blockDim.x + threadIdx.x;
    if (e >= E) return;
    int dst = __ldg(ei + E + e);
    float w = __ldg(ew + e);
    unsigned long long enc =
        (1ull << 40) | (unsigned long long)(unsigned)(w * 16777216.0f + 0.5f);
    unsigned long long old = atomicAdd(&g_degcnt[dst], enc);
    g_rank[e] = (int)(old >> 40);
}

// scan level 1: per-block (512) exclusive-scan of counts via warp shuffles.
__global__ void k_scan1(int N) {
    __shared__ int ws[16];
    int tid  = threadIdx.x;
    int lane = tid & 31, wid = tid >> 5;
    int i = blockIdx.x * SCANB + tid;
    int v = (i < N) ? (int)(g_degcnt[i] >> 40) : 0;
    int orig = v;
#pragma unroll
    for (int off = 1; off < 32; off <<= 1) {
        int t = __shfl_up_sync(0xffffffffu, v, off);
        if (lane >= off) v += t;
    }
    if (lane == 31) ws[wid] = v;
    __syncthreads();
    if (wid == 0) {
        int wv = (lane < 16) ? ws[lane] : 0;
#pragma unroll
        for (int off = 1; off < 16; off <<= 1) {
            int t = __shfl_up_sync(0xffffffffu, wv, off);
            if (lane >= off) wv += t;
        }
        if (lane < 16) ws[lane] = wv;
    }
    __syncthreads();
    int vinc = v + ((wid > 0) ? ws[wid - 1] : 0);
    if (i < N) g_start[i] = vinc - orig;          // exclusive partial
    if (tid == SCANB - 1) g_bsum[blockIdx.x] = vinc;
}

// scan level 2+3: every block redundantly shuffle-scans the <=256 block sums,
// finalizes starts, computes dinv from the packed degree, resets degcnt.
__global__ void k_scan23(int N, int NB, int E) {
    __shared__ int ws[8];
    __shared__ int sx[256];
    int tid  = threadIdx.x;
    int lane = tid & 31, wid = tid >> 5;
    int v = (tid < NB) ? g_bsum[tid] : 0;
    int orig = v;
#pragma unroll
    for (int off = 1; off < 32; off <<= 1) {
        int t = __shfl_up_sync(0xffffffffu, v, off);
        if (lane >= off) v += t;
    }
    if (lane == 31) ws[wid] = v;
    __syncthreads();
    if (wid == 0) {
        int wv = (lane < 8) ? ws[lane] : 0;
#pragma unroll
        for (int off = 1; off < 8; off <<= 1) {
            int t = __shfl_up_sync(0xffffffffu, wv, off);
            if (lane >= off) wv += t;
        }
        if (lane < 8) ws[lane] = wv;
    }
    __syncthreads();
    sx[tid] = v + ((wid > 0) ? ws[wid - 1] : 0) - orig;  // exclusive
    __syncthreads();

    int i = blockIdx.x * blockDim.x + tid;
    if (i == 0) g_start[N] = E;
    if (i >= N) return;
    g_start[i] += sx[i / SCANB];
    unsigned long long dc = g_degcnt[i];
    g_degcnt[i] = 0;                               // restore invariant
    float deg = 1.0f + (float)(dc & 0xFFFFFFFFFFull) * (1.0f / 16777216.0f);
    g_dinv[i] = rsqrtf(deg);
}

// scatter edges into dst-sorted CSR, NO atomics: p = start[dst] + rank[e].
// src-side norm folded in: entry = {src, w * dinv[src]}.
__global__ void k_scatter(const int* __restrict__ ei,
                          const float* __restrict__ ew, int E) {
    int e = blockIdx.x * blockDim.x + threadIdx.x;
    if (e >= E) return;
    int src = __ldg(ei + e);
    int dst = __ldg(ei + E + e);
    float w = __ldg(ew + e) * __ldg(g_dinv + src);
    int p = __ldg(g_start + dst) + g_rank[e];
    g_csr[p] = make_float2(__int_as_float(src), w);
}

// ---------------------------------------------------------------------------
// Register-tiled GEMM (TM=4, BM=128 — measured-best config). No dinv use =>
// independent of the CSR/degree chain (stream-overlappable).
template <int FIN, int FOUT, int LAYER>
__global__ void __launch_bounds__(32 * (FOUT / 4))
k_gemm_tiled(const float* __restrict__ Xin,
             const float* __restrict__ W, int N) {
    constexpr int NCT = FOUT / 4;       // 8 (L1) or 4 (L2)
    constexpr int TM  = 4;
    constexpr int BM  = 32 * TM;        // 128 rows/block
    constexpr int NT  = NCT * 32;

    __shared__ float sW[FIN * FOUT];
    for (int i = threadIdx.x; i < FIN * FOUT / 4; i += NT)
        reinterpret_cast<float4*>(sW)[i] =
            __ldg(reinterpret_cast<const float4*>(W) + i);
    __syncthreads();

    const float* X = (LAYER == 1) ? Xin : reinterpret_cast<const float*>(g_z1);
    const int ci = threadIdx.x % NCT;
    const int ri = threadIdx.x / NCT;
    const int r0 = blockIdx.x * BM + ri * TM;
    const bool full = (r0 + TM <= N);

    float acc[TM][4];
#pragma unroll
    for (int t = 0; t < TM; t++)
#pragma unroll
        for (int j = 0; j < 4; j++) acc[t][j] = 0.0f;

#pragma unroll 4
    for (int k4 = 0; k4 < FIN / 4; k4++) {
        float xr[TM][4];
#pragma unroll
        for (int t = 0; t < TM; t++) {
            float4 v = make_float4(0.f, 0.f, 0.f, 0.f);
            int r = r0 + t;
            if (full || r < N)
                v = __ldg(reinterpret_cast<const float4*>(X + (size_t)r * FIN) + k4);
            xr[t][0] = v.x; xr[t][1] = v.y; xr[t][2] = v.z; xr[t][3] = v.w;
        }
#pragma unroll
        for (int kk = 0; kk < 4; kk++) {
            float4 wv = *reinterpret_cast<const float4*>(
                &sW[(k4 * 4 + kk) * FOUT + ci * 4]);
#pragma unroll
            for (int t = 0; t < TM; t++) {
                float xs = xr[t][kk];
                acc[t][0] += xs * wv.x;
                acc[t][1] += xs * wv.y;
                acc[t][2] += xs * wv.z;
                acc[t][3] += xs * wv.w;
            }
        }
    }

    float4* HS = (LAYER == 1) ? g_hs1 : g_hs2;
#pragma unroll
    for (int t = 0; t < TM; t++) {
        int r = r0 + t;
        if (full || r < N)
            HS[(size_t)r * NCT + ci] = make_float4(acc[t][0], acc[t][1],
                                                   acc[t][2], acc[t][3]);
    }
}

// ---------------------------------------------------------------------------
// CSR aggregation layer 1: warp per node, 4 edge-groups x 8 chunk-threads.
// z1 = relu(s*(sum_e w'*h1[src] + s*h1[node]) + b1)   (s = dinv[node])
__global__ void k_agg1(const float* __restrict__ b1, int N) {
    int warp = (blockIdx.x * blockDim.x + threadIdx.x) >> 5;
    if (warp >= N) return;
    int lane = threadIdx.x & 31;
    int c  = lane & 7;        // feature chunk (float4)
    int eg = lane >> 3;       // edge group 0..3

    int start = __ldg(g_start + warp);
    int cnt   = __ldg(g_start + warp + 1) - start;

    float4 acc = make_float4(0.f, 0.f, 0.f, 0.f);
    for (int k = eg; k < cnt; k += 4) {
        float2 ed = __ldg(g_csr + start + k);
        int   src = __float_as_int(ed.x);
        float w   = ed.y;
        float4 v  = __ldg(g_hs1 + (size_t)src * 8 + c);
        acc.x += w * v.x; acc.y += w * v.y;
        acc.z += w * v.z; acc.w += w * v.w;
    }
#pragma unroll
    for (int m = 8; m <= 16; m <<= 1) {
        acc.x += __shfl_xor_sync(0xffffffffu, acc.x, m);
        acc.y += __shfl_xor_sync(0xffffffffu, acc.y, m);
        acc.z += __shfl_xor_sync(0xffffffffu, acc.z, m);
        acc.w += __shfl_xor_sync(0xffffffffu, acc.w, m);
    }
    if (eg == 0) {
        float  s  = g_dinv[warp];
        float4 h  = __ldg(g_hs1 + (size_t)warp * 8 + c);
        float4 bb = __ldg(reinterpret_cast<const float4*>(b1) + c);
        float4 z;
        z.x = fmaxf(s * (acc.x + s * h.x) + bb.x, 0.0f);
        z.y = fmaxf(s * (acc.y + s * h.y) + bb.y, 0.0f);
        z.z = fmaxf(s * (acc.z + s * h.z) + bb.z, 0.0f);
        z.w = fmaxf(s * (acc.w + s * h.w) + bb.w, 0.0f);
        g_z1[(size_t)warp * 8 + c] = z;
    }
}

// ---------------------------------------------------------------------------
// CSR aggregation layer 2 + fused final linear (16 -> 3).
__global__ void k_agg2_out(const float* __restrict__ b2,
                           const float* __restrict__ Wout,
                           const float* __restrict__ bout,
                           float* __restrict__ out, int N) {
    __shared__ float sW[48];
    __shared__ float sb[3];
    if (threadIdx.x < 48) sW[threadIdx.x] = __ldg(Wout + threadIdx.x);
    if (threadIdx.x < 3)  sb[threadIdx.x] = __ldg(bout + threadIdx.x);
    __syncthreads();

    int warp = (blockIdx.x * blockDim.x + threadIdx.x) >> 5;
    if (warp >= N) return;
    int lane = threadIdx.x & 31;
    int c  = lane & 3;        // feature chunk (float4), 4 chunks = 16 floats
    int eg = lane >> 2;       // edge group 0..7

    int start = __ldg(g_start + warp);
    int cnt   = __ldg(g_start + warp + 1) - start;

    float4 acc = make_float4(0.f, 0.f, 0.f, 0.f);
    for (int k = eg; k < cnt; k += 8) {
        float2 ed = __ldg(g_csr + start + k);
        int   src = __float_as_int(ed.x);
        float w   = ed.y;
        float4 v  = __ldg(g_hs2 + (size_t)src * 4 + c);
        acc.x += w * v.x; acc.y += w * v.y;
        acc.z += w * v.z; acc.w += w * v.w;
    }
#pragma unroll
    for (int m = 4; m <= 16; m <<= 1) {
        acc.x += __shfl_xor_sync(0xffffffffu, acc.x, m);
        acc.y += __shfl_xor_sync(0xffffffffu, acc.y, m);
        acc.z += __shfl_xor_sync(0xffffffffu, acc.z, m);
        acc.w += __shfl_xor_sync(0xffffffffu, acc.w, m);
    }
    // lanes 0..3 hold the 4 final chunks
    float  s  = g_dinv[warp];
    float4 h  = __ldg(g_hs2 + (size_t)warp * 4 + c);
    float4 bb = __ldg(reinterpret_cast<const float4*>(b2) + c);
    float z[4];
    z[0] = fmaxf(s * (acc.x + s * h.x) + bb.x, 0.0f);
    z[1] = fmaxf(s * (acc.y + s * h.y) + bb.y, 0.0f);
    z[2] = fmaxf(s * (acc.z + s * h.z) + bb.z, 0.0f);
    z[3] = fmaxf(s * (acc.w + s * h.w) + bb.w, 0.0f);

    float a0 = 0.f, a1 = 0.f, a2 = 0.f;
#pragma unroll
    for (int q = 0; q < 4; q++) {
        int kk = c * 4 + q;
        a0 += z[q] * sW[kk * 3 + 0];
        a1 += z[q] * sW[kk * 3 + 1];
        a2 += z[q] * sW[kk * 3 + 2];
    }
#pragma unroll
    for (int m = 1; m <= 2; m <<= 1) {
        a0 += __shfl_xor_sync(0xffffffffu, a0, m);
        a1 += __shfl_xor_sync(0xffffffffu, a1, m);
        a2 += __shfl_xor_sync(0xffffffffu, a2, m);
    }
    if (lane == 0) {
        float* o = out + (size_t)warp * 3;
        o[0] = a0 + sb[0]; o[1] = a1 + sb[1]; o[2] = a2 + sb[2];
    }
}

// ---------------------------------------------------------------------------
extern "C" void kernel_launch(void* const* d_in, const int* in_sizes, int n_in,
                              void* d_out, int out_size) {
    const float* x    = (const float*)d_in[0];
    const int*   ei   = (const int*)d_in[1];     // int32 [2, E]
    const float* ew   = (const float*)d_in[2];
    const float* W1   = (const float*)d_in[3];
    const float* b1   = (const float*)d_in[4];
    const float* W2   = (const float*)d_in[5];
    const float* b2   = (const float*)d_in[6];
    const float* Wout = (const float*)d_in[7];
    const float* bout = (const float*)d_in[8];
    float*       out  = (float*)d_out;

    const int N  = in_sizes[0] / 128;
    const int E  = in_sizes[2];
    const int NB = (N + SCANB - 1) / SCANB;

    const int B = 256;
    auto blocks = [B](long long n) { return (unsigned)((n + B - 1) / B); };

    // Side stream + events, created once on the (non-capturing) correctness
    // call; reused during capture (event fork/join pattern).
    static cudaStream_t s_side = nullptr;
    static cudaEvent_t  s_ev0 = nullptr, s_ev1 = nullptr;
    if (s_side == nullptr) {
        cudaStreamCreateWithFlags(&s_side, cudaStreamNonBlocking);
        cudaEventCreateWithFlags(&s_ev0, cudaEventDisableTiming);
        cudaEventCreateWithFlags(&s_ev1, cudaEventDisableTiming);
    }

    // Fork: gemm1 (independent of the CSR chain) on the side stream.
    cudaEventRecord(s_ev0, 0);
    cudaStreamWaitEvent(s_side, s_ev0, 0);
    k_gemm_tiled<128, 32, 1><<<(N + 127) / 128, 256, 0, s_side>>>(x, W1, N);
    cudaEventRecord(s_ev1, s_side);

    // Main stream: CSR build (+ dinv), overlapped with gemm1.
    k_hist   <<<blocks(E), B>>>(ei, ew, E);
    k_scan1  <<<NB, SCANB>>>(N);
    k_scan23 <<<blocks(N), B>>>(N, NB, E);
    k_scatter<<<blocks(E), B>>>(ei, ew, E);

    // Join, then the serial tail.
    cudaStreamWaitEvent(0, s_ev1, 0);
    k_agg1<<<blocks((long long)N * 32), B>>>(b1, N);
    k_gemm_tiled<32, 16, 2><<<(N + 127) / 128, 128>>>(nullptr, W2, N);
    k_agg2_out<<<blocks((long long)N * 32), B>>>(b2, Wout, bout, out, N);
}

// round 12
// speedup vs baseline: 1.2232x; 1.0654x over previous
#include <cuda_runtime.h>
#include <cuda_fp16.h>
#include <cstdint>

// Problem-shape capacities (fixed by the dataset: N=100000, E=3200000)
#define NCAP 100000
#define ECAP 3200000
#define SCANB 512                            // level-1 scan block size
#define NBMAX ((NCAP + SCANB - 1) / SCANB)   // 196 <= 256

// Static device scratch. Zero-filled at module load; kernels restore "zero"
// invariants after use so every execution sees identical initial state.
__device__ unsigned long long g_degcnt[NCAP];  // hi24: count, lo40: sum(w)*2^24
__device__ float  g_dinv  [NCAP];
__device__ int    g_start [NCAP + 1];   // CSR row starts (+ total at [N])
__device__ int    g_bsum  [NBMAX];      // scan block sums
__device__ int    g_rank  [ECAP];       // per-edge rank within dst bucket
__device__ float2 g_csr   [ECAP];       // dst-sorted: {src bits, w*dinv[src]}
__device__ int4   g_hs1h  [NCAP * 4];   // h1 = x@W1, fp16 (32 halves = 64B/row)
__device__ float4 g_z1    [NCAP * 8];   // relu layer-1 output (fp32)
__device__ int4   g_hs2h  [NCAP * 2];   // h2 = z1@W2, fp16 (16 halves = 32B/row)

// ---------------------------------------------------------------------------
// histogram: one packed u64 atomic gives count, weighted degree, AND the
// edge's rank within its dst bucket (returned old value).
__global__ void k_hist(const int* __restrict__ ei,
                       const float* __restrict__ ew, int E) {
    int e = blockIdx.x * blockDim.x + threadIdx.x;
    if (e >= E) return;
    int dst = __ldg(ei + E + e);
    float w = __ldg(ew + e);
    unsigned long long enc =
        (1ull << 40) | (unsigned long long)(unsigned)(w * 16777216.0f + 0.5f);
    unsigned long long old = atomicAdd(&g_degcnt[dst], enc);
    g_rank[e] = (int)(old >> 40);
}

// scan level 1: per-block (512) exclusive-scan of counts via warp shuffles.
__global__ void k_scan1(int N) {
    __shared__ int ws[16];
    int tid  = threadIdx.x;
    int lane = tid & 31, wid = tid >> 5;
    int i = blockIdx.x * SCANB + tid;
    int v = (i < N) ? (int)(g_degcnt[i] >> 40) : 0;
    int orig = v;
#pragma unroll
    for (int off = 1; off < 32; off <<= 1) {
        int t = __shfl_up_sync(0xffffffffu, v, off);
        if (lane >= off) v += t;
    }
    if (lane == 31) ws[wid] = v;
    __syncthreads();
    if (wid == 0) {
        int wv = (lane < 16) ? ws[lane] : 0;
#pragma unroll
        for (int off = 1; off < 16; off <<= 1) {
            int t = __shfl_up_sync(0xffffffffu, wv, off);
            if (lane >= off) wv += t;
        }
        if (lane < 16) ws[lane] = wv;
    }
    __syncthreads();
    int vinc = v + ((wid > 0) ? ws[wid - 1] : 0);
    if (i < N) g_start[i] = vinc - orig;          // exclusive partial
    if (tid == SCANB - 1) g_bsum[blockIdx.x] = vinc;
}

// scan level 2+3: each block shuffle-scans the <=256 block sums, then
// finalizes 2 nodes per thread (512-node span = one scan1 block).
__global__ void k_scan23(int N, int NB, int E) {
    __shared__ int ws[8];
    __shared__ int sx[256];
    int tid  = threadIdx.x;
    int lane = tid & 31, wid = tid >> 5;
    int v = (tid < NB) ? g_bsum[tid] : 0;
    int orig = v;
#pragma unroll
    for (int off = 1; off < 32; off <<= 1) {
        int t = __shfl_up_sync(0xffffffffu, v, off);
        if (lane >= off) v += t;
    }
    if (lane == 31) ws[wid] = v;
    __syncthreads();
    if (wid == 0) {
        int wv = (lane < 8) ? ws[lane] : 0;
#pragma unroll
        for (int off = 1; off < 8; off <<= 1) {
            int t = __shfl_up_sync(0xffffffffu, wv, off);
            if (lane >= off) wv += t;
        }
        if (lane < 8) ws[lane] = wv;
    }
    __syncthreads();
    sx[tid] = v + ((wid > 0) ? ws[wid - 1] : 0) - orig;  // exclusive
    __syncthreads();

    if (blockIdx.x == 0 && tid == 0) g_start[N] = E;
#pragma unroll
    for (int half = 0; half < 2; half++) {
        int i = blockIdx.x * 512 + half * 256 + tid;
        if (i >= N) continue;
        g_start[i] += sx[i / SCANB];
        unsigned long long dc = g_degcnt[i];
        g_degcnt[i] = 0;                           // restore invariant
        float deg = 1.0f + (float)(dc & 0xFFFFFFFFFFull) * (1.0f / 16777216.0f);
        g_dinv[i] = rsqrtf(deg);
    }
}

// scatter edges into dst-sorted CSR, NO atomics: p = start[dst] + rank[e].
__global__ void k_scatter(const int* __restrict__ ei,
                          const float* __restrict__ ew, int E) {
    int e = blockIdx.x * blockDim.x + threadIdx.x;
    if (e >= E) return;
    int src = __ldg(ei + e);
    int dst = __ldg(ei + E + e);
    float w = __ldg(ew + e) * __ldg(g_dinv + src);
    int p = __ldg(g_start + dst) + g_rank[e];
    g_csr[p] = make_float2(__int_as_float(src), w);
}

// ---------------------------------------------------------------------------
// Register-tiled GEMM (TM=4, BM=128), fp16 epilogue store.
// LAYER==1: X = raw input x -> g_hs1h. LAYER==2: X = g_z1 -> g_hs2h.
template <int FIN, int FOUT, int LAYER>
__global__ void __launch_bounds__(32 * (FOUT / 4))
k_gemm_tiled(const float* __restrict__ Xin,
             const float* __restrict__ W, int N) {
    constexpr int NCT = FOUT / 4;       // 8 (L1) or 4 (L2)
    constexpr int TM  = 4;
    constexpr int BM  = 32 * TM;        // 128 rows/block
    constexpr int NT  = NCT * 32;

    __shared__ float sW[FIN * FOUT];
    for (int i = threadIdx.x; i < FIN * FOUT / 4; i += NT)
        reinterpret_cast<float4*>(sW)[i] =
            __ldg(reinterpret_cast<const float4*>(W) + i);
    __syncthreads();

    const float* X = (LAYER == 1) ? Xin : reinterpret_cast<const float*>(g_z1);
    const int ci = threadIdx.x % NCT;
    const int ri = threadIdx.x / NCT;
    const int r0 = blockIdx.x * BM + ri * TM;
    const bool full = (r0 + TM <= N);

    float acc[TM][4];
#pragma unroll
    for (int t = 0; t < TM; t++)
#pragma unroll
        for (int j = 0; j < 4; j++) acc[t][j] = 0.0f;

#pragma unroll 4
    for (int k4 = 0; k4 < FIN / 4; k4++) {
        float xr[TM][4];
#pragma unroll
        for (int t = 0; t < TM; t++) {
            float4 v = make_float4(0.f, 0.f, 0.f, 0.f);
            int r = r0 + t;
            if (full || r < N)
                v = __ldg(reinterpret_cast<const float4*>(X + (size_t)r * FIN) + k4);
            xr[t][0] = v.x; xr[t][1] = v.y; xr[t][2] = v.z; xr[t][3] = v.w;
        }
#pragma unroll
        for (int kk = 0; kk < 4; kk++) {
            float4 wv = *reinterpret_cast<const float4*>(
                &sW[(k4 * 4 + kk) * FOUT + ci * 4]);
#pragma unroll
            for (int t = 0; t < TM; t++) {
                float xs = xr[t][kk];
                acc[t][0] += xs * wv.x;
                acc[t][1] += xs * wv.y;
                acc[t][2] += xs * wv.z;
                acc[t][3] += xs * wv.w;
            }
        }
    }

    // fp16 store: 4 floats -> 2 half2 = 8B (uint2), row = FOUT halves.
    uint2* HS = (LAYER == 1) ? reinterpret_cast<uint2*>(g_hs1h)
                             : reinterpret_cast<uint2*>(g_hs2h);
#pragma unroll
    for (int t = 0; t < TM; t++) {
        int r = r0 + t;
        if (full || r < N) {
            __half2 lo = __float22half2_rn(make_float2(acc[t][0], acc[t][1]));
            __half2 hi = __float22half2_rn(make_float2(acc[t][2], acc[t][3]));
            uint2 pk;
            pk.x = *reinterpret_cast<unsigned*>(&lo);
            pk.y = *reinterpret_cast<unsigned*>(&hi);
            HS[(size_t)r * NCT + ci] = pk;
        }
    }
}

// helper: int4 of 8 halves -> 8 floats
__device__ __forceinline__ void unpack8(const int4& p, float* f) {
    __half2 h0 = *reinterpret_cast<const __half2*>(&p.x);
    __half2 h1 = *reinterpret_cast<const __half2*>(&p.y);
    __half2 h2 = *reinterpret_cast<const __half2*>(&p.z);
    __half2 h3 = *reinterpret_cast<const __half2*>(&p.w);
    float2 a = __half22float2(h0), b = __half22float2(h1);
    float2 c = __half22float2(h2), d = __half22float2(h3);
    f[0] = a.x; f[1] = a.y; f[2] = b.x; f[3] = b.y;
    f[4] = c.x; f[5] = c.y; f[6] = d.x; f[7] = d.y;
}

// ---------------------------------------------------------------------------
// CSR aggregation layer 1: warp per node, 8 edge-groups x 4 chunk-threads.
// Each chunk-thread handles 8 features (one int4 of halves).
// z1 = relu(s*(sum_e w'*h1[src] + s*h1[node]) + b1)   (fp32 accumulation)
__global__ void k_agg1(const float* __restrict__ b1, int N) {
    int warp = (blockIdx.x * blockDim.x + threadIdx.x) >> 5;
    if (warp >= N) return;
    int lane = threadIdx.x & 31;
    int c  = lane & 3;        // feature chunk: 8 halves (16B)
    int eg = lane >> 2;       // edge group 0..7

    int start = __ldg(g_start + warp);
    int cnt   = __ldg(g_start + warp + 1) - start;

    float acc[8];
#pragma unroll
    for (int q = 0; q < 8; q++) acc[q] = 0.0f;

    for (int k = eg; k < cnt; k += 8) {
        float2 ed = __ldg(g_csr + start + k);
        int   src = __float_as_int(ed.x);
        float w   = ed.y;
        int4 p = __ldg(g_hs1h + (size_t)src * 4 + c);
        float f[8]; unpack8(p, f);
#pragma unroll
        for (int q = 0; q < 8; q++) acc[q] += w * f[q];
    }
#pragma unroll
    for (int m = 4; m <= 16; m <<= 1)
#pragma unroll
        for (int q = 0; q < 8; q++)
            acc[q] += __shfl_xor_sync(0xffffffffu, acc[q], m);

    if (eg == 0) {
        float s = g_dinv[warp];
        int4 p = __ldg(g_hs1h + (size_t)warp * 4 + c);
        float h[8]; unpack8(p, h);
        float4 b0 = __ldg(reinterpret_cast<const float4*>(b1) + c * 2);
        float4 b1v = __ldg(reinterpret_cast<const float4*>(b1) + c * 2 + 1);
        float bb[8] = {b0.x, b0.y, b0.z, b0.w, b1v.x, b1v.y, b1v.z, b1v.w};
        float z[8];
#pragma unroll
        for (int q = 0; q < 8; q++)
            z[q] = fmaxf(s * (acc[q] + s * h[q]) + bb[q], 0.0f);
        float4* Z = g_z1 + (size_t)warp * 8 + c * 2;
        Z[0] = make_float4(z[0], z[1], z[2], z[3]);
        Z[1] = make_float4(z[4], z[5], z[6], z[7]);
    }
}

// ---------------------------------------------------------------------------
// CSR aggregation layer 2 + fused final linear (16 -> 3).
// 16 edge-groups x 2 chunk-threads (8 halves each).
__global__ void k_agg2_out(const float* __restrict__ b2,
                           const float* __restrict__ Wout,
                           const float* __restrict__ bout,
                           float* __restrict__ out, int N) {
    __shared__ float sW[48];
    __shared__ float sb[3];
    if (threadIdx.x < 48) sW[threadIdx.x] = __ldg(Wout + threadIdx.x);
    if (threadIdx.x < 3)  sb[threadIdx.x] = __ldg(bout + threadIdx.x);
    __syncthreads();

    int warp = (blockIdx.x * blockDim.x + threadIdx.x) >> 5;
    if (warp >= N) return;
    int lane = threadIdx.x & 31;
    int c  = lane & 1;        // feature chunk: 8 halves (16B), 2 chunks = 16
    int eg = lane >> 1;       // edge group 0..15

    int start = __ldg(g_start + warp);
    int cnt   = __ldg(g_start + warp + 1) - start;

    float acc[8];
#pragma unroll
    for (int q = 0; q < 8; q++) acc[q] = 0.0f;

    for (int k = eg; k < cnt; k += 16) {
        float2 ed = __ldg(g_csr + start + k);
        int   src = __float_as_int(ed.x);
        float w   = ed.y;
        int4 p = __ldg(g_hs2h + (size_t)src * 2 + c);
        float f[8]; unpack8(p, f);
#pragma unroll
        for (int q = 0; q < 8; q++) acc[q] += w * f[q];
    }
#pragma unroll
    for (int m = 2; m <= 16; m <<= 1)
#pragma unroll
        for (int q = 0; q < 8; q++)
            acc[q] += __shfl_xor_sync(0xffffffffu, acc[q], m);

    // lanes 0..1 hold the 2 chunks
    float s = g_dinv[warp];
    int4 p = __ldg(g_hs2h + (size_t)warp * 2 + c);
    float h[8]; unpack8(p, h);
    float4 b0 = __ldg(reinterpret_cast<const float4*>(b2) + c * 2);
    float4 b1v = __ldg(reinterpret_cast<const float4*>(b2) + c * 2 + 1);
    float bb[8] = {b0.x, b0.y, b0.z, b0.w, b1v.x, b1v.y, b1v.z, b1v.w};

    float a0 = 0.f, a1 = 0.f, a2 = 0.f;
#pragma unroll
    for (int q = 0; q < 8; q++) {
        float z = fmaxf(s * (acc[q] + s * h[q]) + bb[q], 0.0f);
        int kk = c * 8 + q;
        a0 += z * sW[kk * 3 + 0];
        a1 += z * sW[kk * 3 + 1];
        a2 += z * sW[kk * 3 + 2];
    }
    a0 += __shfl_xor_sync(0xffffffffu, a0, 1);
    a1 += __shfl_xor_sync(0xffffffffu, a1, 1);
    a2 += __shfl_xor_sync(0xffffffffu, a2, 1);
    if (lane == 0) {
        float* o = out + (size_t)warp * 3;
        o[0] = a0 + sb[0]; o[1] = a1 + sb[1]; o[2] = a2 + sb[2];
    }
}

// ---------------------------------------------------------------------------
extern "C" void kernel_launch(void* const* d_in, const int* in_sizes, int n_in,
                              void* d_out, int out_size) {
    const float* x    = (const float*)d_in[0];
    const int*   ei   = (const int*)d_in[1];     // int32 [2, E]
    const float* ew   = (const float*)d_in[2];
    const float* W1   = (const float*)d_in[3];
    const float* b1   = (const float*)d_in[4];
    const float* W2   = (const float*)d_in[5];
    const float* b2   = (const float*)d_in[6];
    const float* Wout = (const float*)d_in[7];
    const float* bout = (const float*)d_in[8];
    float*       out  = (float*)d_out;

    const int N  = in_sizes[0] / 128;
    const int E  = in_sizes[2];
    const int NB = (N + SCANB - 1) / SCANB;

    const int B = 256;
    auto blocks = [B](long long n) { return (unsigned)((n + B - 1) / B); };

    static cudaStream_t s_side = nullptr;
    static cudaEvent_t  s_ev0 = nullptr, s_ev1 = nullptr;
    if (s_side == nullptr) {
        cudaStreamCreateWithFlags(&s_side, cudaStreamNonBlocking);
        cudaEventCreateWithFlags(&s_ev0, cudaEventDisableTiming);
        cudaEventCreateWithFlags(&s_ev1, cudaEventDisableTiming);
    }

    // Fork: gemm1 (independent of the CSR chain) on the side stream.
    cudaEventRecord(s_ev0, 0);
    cudaStreamWaitEvent(s_side, s_ev0, 0);
    k_gemm_tiled<128, 32, 1><<<(N + 127) / 128, 256, 0, s_side>>>(x, W1, N);
    cudaEventRecord(s_ev1, s_side);

    // Main stream: CSR build (+ dinv), overlapped with gemm1.
    k_hist   <<<blocks(E), B>>>(ei, ew, E);
    k_scan1  <<<NB, SCANB>>>(N);
    k_scan23 <<<(unsigned)((N + 511) / 512), 256>>>(N, NB, E);
    k_scatter<<<blocks(E), B>>>(ei, ew, E);

    // Join, then the serial tail.
    cudaStreamWaitEvent(0, s_ev1, 0);
    k_agg1<<<blocks((long long)N * 32), B>>>(b1, N);
    k_gemm_tiled<32, 16, 2><<<(N + 127) / 128, 128>>>(nullptr, W2, N);
    k_agg2_out<<<blocks((long long)N * 32), B>>>(b2, Wout, bout, out, N);
}